// round 13
// baseline (speedup 1.0000x reference)
#include <cuda_runtime.h>
#include <cuda_bf16.h>

#define N_NODES 30000
#define N_EDGES 480000
#define D 128
#define EPSF 1e-7f
#define SIN_STRIDE 34   // 34 floats: 8B-aligned rows (136B) for direct LDS.64 pairs

// ---------------- scratch (device globals; no allocation allowed) ----------------
__device__ float g_hA [N_NODES * D];
__device__ float g_hB [N_NODES * D];
__device__ float g_pre[N_NODES * D];      // (agg + h) per layer, GEMM input

// CSR build scratch
__device__ int  g_cnt[N_NODES];
__device__ int  g_cur[N_NODES];
__device__ int  g_row[N_NODES + 1];
__device__ int2 g_edge[N_EDGES];          // {src, float_bits(edge_attr)}

// ---------------- packed f32x2 helpers ------------------------------------------
__device__ __forceinline__ unsigned long long ffma2(
    unsigned long long a, unsigned long long b, unsigned long long c)
{
    unsigned long long d;
    asm("fma.rn.f32x2 %0, %1, %2, %3;" : "=l"(d) : "l"(a), "l"(b), "l"(c));
    return d;
}
__device__ __forceinline__ unsigned long long pack2(float lo, float hi) {
    unsigned long long p;
    asm("mov.b64 %0, {%1, %2};" : "=l"(p) : "r"(__float_as_uint(lo)), "r"(__float_as_uint(hi)));
    return p;
}
__device__ __forceinline__ void unpack2(unsigned long long p, float& lo, float& hi) {
    unsigned int l, h;
    asm("mov.b64 {%0, %1}, %2;" : "=r"(l), "=r"(h) : "l"(p));
    lo = __uint_as_float(l); hi = __uint_as_float(h);
}

// ---------------- CSR build ------------------------------------------------------
__global__ void __launch_bounds__(256) csr_zero() {
    int i = blockIdx.x * 256 + threadIdx.x;
    if (i < N_NODES) { g_cnt[i] = 0; g_cur[i] = 0; }
}

__global__ void __launch_bounds__(256) csr_hist(const int* __restrict__ ei) {
    int e = blockIdx.x * 256 + threadIdx.x;
    if (e < N_EDGES) atomicAdd(&g_cnt[ei[N_EDGES + e]], 1);
}

// single-block exclusive scan of g_cnt -> g_row (30000 elems, 1024 threads x 30)
__global__ void __launch_bounds__(1024) csr_scan() {
    __shared__ int part[1024];
    const int t = threadIdx.x;
    const int CH = 30;
    int base = t * CH;
    int local[CH];
    int sum = 0;
    #pragma unroll
    for (int i = 0; i < CH; i++) {
        int idx = base + i;
        int v = (idx < N_NODES) ? g_cnt[idx] : 0;
        local[i] = sum;
        sum += v;
    }
    part[t] = sum;
    __syncthreads();
    for (int off = 1; off < 1024; off <<= 1) {
        int v = (t >= off) ? part[t - off] : 0;
        __syncthreads();
        part[t] += v;
        __syncthreads();
    }
    int exoff = part[t] - sum;
    #pragma unroll
    for (int i = 0; i < CH; i++) {
        int idx = base + i;
        if (idx < N_NODES) g_row[idx] = exoff + local[i];
    }
    if (t == 1023) g_row[N_NODES] = part[1023];
}

__global__ void __launch_bounds__(256) csr_scatter(
    const int* __restrict__ ei, const float* __restrict__ ea)
{
    int e = blockIdx.x * 256 + threadIdx.x;
    if (e >= N_EDGES) return;
    int s = ei[e];
    int d = ei[N_EDGES + e];
    int pos = g_row[d] + atomicAdd(&g_cur[d], 1);
    g_edge[pos] = make_int2(s, __float_as_int(ea[e]));
}

// ---------------- packed GEMM tail: out[nb..nb+31][:] = sInT^T @ W + bias -------
__device__ __forceinline__ void gemm128_tail_T(
    float (*sInT)[SIN_STRIDE], float (*sW)[128],
    const float* __restrict__ W, const float* __restrict__ bias,
    float* __restrict__ out, int nb, int t)
{
    unsigned long long accp[16];
    #pragma unroll
    for (int j = 0; j < 16; j++) accp[j] = 0ull;

    for (int k0 = 0; k0 < 128; k0 += 64) {
        __syncthreads();
        const float4* Wsrc = (const float4*)(W + k0 * 128);
        float4*       Wdst = (float4*)&sW[0][0];
        #pragma unroll
        for (int i = 0; i < 16; i++) Wdst[t + i * 128] = Wsrc[t + i * 128];
        __syncthreads();

        #pragma unroll 4
        for (int k = 0; k < 64; k++) {
            float w = sW[k][t];
            unsigned long long wp = pack2(w, w);
            const unsigned long long* arow =
                (const unsigned long long*)&sInT[k0 + k][0];
            #pragma unroll
            for (int j = 0; j < 16; j++)
                accp[j] = ffma2(arow[j], wp, accp[j]);
        }
    }
    float b = bias[t];
    #pragma unroll
    for (int j = 0; j < 16; j++) {
        float lo, hi;
        unpack2(accp[j], lo, hi);
        int n0 = nb + 2 * j;
        int n1 = n0 + 1;
        if (n0 < N_NODES) out[n0 * D + t] = lo + b;
        if (n1 < N_NODES) out[n1 * D + t] = hi + b;
    }
}

// ---------------- node encoder: h0 = relu(x@Wn1+bn1)@Wn2+bn2 -> g_hA ------------
__global__ void __launch_bounds__(128) node_encoder(
    const float* __restrict__ x,
    const float* __restrict__ Wn1, const float* __restrict__ bn1,
    const float* __restrict__ Wn2, const float* __restrict__ bn2)
{
    __shared__ float sInT[128][SIN_STRIDE];
    __shared__ float sW  [64][128];
    int nb = blockIdx.x * 32;
    int t  = threadIdx.x;

    float w[7];
    #pragma unroll
    for (int j = 0; j < 7; j++) w[j] = Wn1[j * D + t];
    float b1 = bn1[t];

    for (int n = 0; n < 32; n++) {
        int node = nb + n;
        float v = 0.f;
        if (node < N_NODES) {
            float s = b1;
            #pragma unroll
            for (int j = 0; j < 7; j++) s = fmaf(x[node * 7 + j], w[j], s);
            v = fmaxf(s, 0.f);
        }
        sInT[t][n] = v;
    }
    gemm128_tail_T(sInT, sW, Wn2, bn2, g_hA, nb, t);
}

// ---------------- branchless online softmax update (4 channels) ------------------
__device__ __forceinline__ void smax_upd(
    const float4& hv, float a, const float4& wv, const float4& bv,
    float* m, float* d, float* n)
{
    float msg[4];
    msg[0] = fmaxf(fmaf(a, wv.x, hv.x + bv.x), 0.f) + EPSF;
    msg[1] = fmaxf(fmaf(a, wv.y, hv.y + bv.y), 0.f) + EPSF;
    msg[2] = fmaxf(fmaf(a, wv.z, hv.z + bv.z), 0.f) + EPSF;
    msg[3] = fmaxf(fmaf(a, wv.w, hv.w + bv.w), 0.f) + EPSF;
    #pragma unroll
    for (int c = 0; c < 4; c++) {
        float mn = fmaxf(m[c], msg[c]);
        float eo = __expf(m[c]   - mn);
        float en = __expf(msg[c] - mn);
        d[c] = fmaf(d[c], eo, en);
        n[c] = fmaf(n[c], eo, en * msg[c]);
        m[c] = mn;
    }
}

// ---------------- gather + online segment softmax (warp per dst node) -----------
// 4-wide batched gather: 4 independent edge-index loads, then 4 h-row gathers in
// flight together (MLP=4), then math for all 4. Scalar tail for deg%4.
__global__ void __launch_bounds__(256) genconv_gather(
    int hsel, const float* __restrict__ We, const float* __restrict__ be)
{
    const float* __restrict__ h = hsel ? g_hB : g_hA;
    int node = blockIdx.x * 8 + (threadIdx.x >> 5);
    if (node >= N_NODES) return;
    int lane = threadIdx.x & 31;
    int q    = lane << 2;

    int beg = g_row[node];
    int end = g_row[node + 1];

    float4 wv = *(const float4*)(We + q);
    float4 bv = *(const float4*)(be + q);

    float m[4] = {-1e30f, -1e30f, -1e30f, -1e30f};
    float d[4] = {0.f, 0.f, 0.f, 0.f};
    float n[4] = {0.f, 0.f, 0.f, 0.f};

    int k = beg;
    for (; k + 4 <= end; k += 4) {
        int2 e0 = g_edge[k + 0];
        int2 e1 = g_edge[k + 1];
        int2 e2 = g_edge[k + 2];
        int2 e3 = g_edge[k + 3];
        float4 h0 = *(const float4*)(h + e0.x * D + q);
        float4 h1 = *(const float4*)(h + e1.x * D + q);
        float4 h2 = *(const float4*)(h + e2.x * D + q);
        float4 h3 = *(const float4*)(h + e3.x * D + q);
        smax_upd(h0, __int_as_float(e0.y), wv, bv, m, d, n);
        smax_upd(h1, __int_as_float(e1.y), wv, bv, m, d, n);
        smax_upd(h2, __int_as_float(e2.y), wv, bv, m, d, n);
        smax_upd(h3, __int_as_float(e3.y), wv, bv, m, d, n);
    }
    for (; k < end; k++) {
        int2 e = g_edge[k];
        float4 hv = *(const float4*)(h + e.x * D + q);
        smax_upd(hv, __int_as_float(e.y), wv, bv, m, d, n);
    }

    float4 hn = *(const float4*)(h + node * D + q);
    float4 o;
    o.x = (d[0] > 0.f ? n[0] / d[0] : 0.f) + hn.x;
    o.y = (d[1] > 0.f ? n[1] / d[1] : 0.f) + hn.y;
    o.z = (d[2] > 0.f ? n[2] / d[2] : 0.f) + hn.z;
    o.w = (d[3] > 0.f ? n[3] / d[3] : 0.f) + hn.w;
    *(float4*)(g_pre + node * D + q) = o;
}

// ---------------- node update: h_out = g_pre @ Wg + bg --------------------------
__global__ void __launch_bounds__(128) node_update(
    int hsel, const float* __restrict__ Wg_l, const float* __restrict__ bg_l)
{
    float* h_out = hsel ? g_hA : g_hB;

    __shared__ float sInT[128][SIN_STRIDE];
    __shared__ float sW  [64][128];
    int nb = blockIdx.x * 32;
    int t  = threadIdx.x;

    for (int n = 0; n < 32; n++) {
        int node = nb + n;
        sInT[t][n] = (node < N_NODES) ? g_pre[node * D + t] : 0.f;
    }
    gemm128_tail_T(sInT, sW, Wg_l, bg_l, h_out, nb, t);
}

// ---------------- output head: out = h @ Wo + bo  (warp per node) ---------------
__global__ void __launch_bounds__(256) head_kernel(
    const float* __restrict__ Wo, const float* __restrict__ bo,
    float* __restrict__ out)
{
    int warp = (blockIdx.x * 256 + threadIdx.x) >> 5;
    int lane = threadIdx.x & 31;
    if (warp >= N_NODES) return;
    const float* row = g_hA + warp * D;   // after 4 layers h lives in g_hA

    float a0 = 0.f, a1 = 0.f, a2 = 0.f;
    #pragma unroll
    for (int k = lane; k < D; k += 32) {
        float v = row[k];
        a0 = fmaf(v, Wo[k * 3 + 0], a0);
        a1 = fmaf(v, Wo[k * 3 + 1], a1);
        a2 = fmaf(v, Wo[k * 3 + 2], a2);
    }
    #pragma unroll
    for (int off = 16; off; off >>= 1) {
        a0 += __shfl_down_sync(0xffffffffu, a0, off);
        a1 += __shfl_down_sync(0xffffffffu, a1, off);
        a2 += __shfl_down_sync(0xffffffffu, a2, off);
    }
    if (lane == 0) {
        out[warp * 3 + 0] = a0 + bo[0];
        out[warp * 3 + 1] = a1 + bo[1];
        out[warp * 3 + 2] = a2 + bo[2];
    }
}

// ---------------- launch --------------------------------------------------------
extern "C" void kernel_launch(void* const* d_in, const int* in_sizes, int n_in,
                              void* d_out, int out_size)
{
    const float* x   = (const float*)d_in[0];
    const int*   ei  = (const int*)  d_in[1];
    const float* ea  = (const float*)d_in[2];
    const float* Wn1 = (const float*)d_in[3];
    const float* bn1 = (const float*)d_in[4];
    const float* Wn2 = (const float*)d_in[5];
    const float* bn2 = (const float*)d_in[6];
    const float* We  = (const float*)d_in[7];
    const float* be  = (const float*)d_in[8];
    const float* Wg  = (const float*)d_in[9];
    const float* bg  = (const float*)d_in[10];
    const float* Wo  = (const float*)d_in[11];
    const float* bo  = (const float*)d_in[12];
    float* out = (float*)d_out;

    const int NODE_BLOCKS   = (N_NODES + 31) / 32;        // 938
    const int EDGE_BLOCKS   = (N_EDGES + 255) / 256;      // 1875
    const int CNT_BLOCKS    = (N_NODES + 255) / 256;      // 118
    const int GATHER_BLOCKS = (N_NODES + 7) / 8;          // 3750 (8 warps/block)

    // CSR build (graph constant; recomputed every call for determinism)
    csr_zero   <<<CNT_BLOCKS, 256>>>();
    csr_hist   <<<EDGE_BLOCKS, 256>>>(ei);
    csr_scan   <<<1, 1024>>>();
    csr_scatter<<<EDGE_BLOCKS, 256>>>(ei, ea);

    node_encoder<<<NODE_BLOCKS, 128>>>(x, Wn1, bn1, Wn2, bn2);

    for (int l = 0; l < 4; l++) {
        int hsel = l & 1;   // 0: h in g_hA, 1: h in g_hB
        genconv_gather<<<GATHER_BLOCKS, 256>>>(hsel, We, be);
        node_update   <<<NODE_BLOCKS, 128>>>(hsel, Wg + (size_t)l * D * D, bg + (size_t)l * D);
    }

    head_kernel<<<(N_NODES * 32 + 255) / 256, 256>>>(Wo, bo, out);
}

// round 14
// speedup vs baseline: 1.2036x; 1.2036x over previous
#include <cuda_runtime.h>
#include <cuda_bf16.h>

#define N_NODES 30000
#define N_EDGES 480000
#define D 128
#define EPSF 1e-7f
#define SIN_STRIDE 34   // 34 floats: 8B-aligned rows (136B) for direct LDS.64 pairs
#define LOG2E 1.4426950408889634f
#define LN2   0.6931471805599453f
#define E2    (EPSF * LOG2E)

// ---------------- scratch (device globals; no allocation allowed) ----------------
__device__ float g_hA [N_NODES * D];
__device__ float g_hB [N_NODES * D];
__device__ float g_hb2[N_NODES * D];      // (h + be) * log2e, rebuilt each layer
__device__ float g_pre[N_NODES * D];      // (agg + h) per layer, GEMM input

// CSR build scratch
__device__ int  g_cnt[N_NODES];
__device__ int  g_cur[N_NODES];
__device__ int  g_row[N_NODES + 1];
__device__ int2 g_edge[N_EDGES];          // {src, float_bits(edge_attr)}

// ---------------- packed f32x2 helpers ------------------------------------------
__device__ __forceinline__ unsigned long long ffma2(
    unsigned long long a, unsigned long long b, unsigned long long c)
{
    unsigned long long d;
    asm("fma.rn.f32x2 %0, %1, %2, %3;" : "=l"(d) : "l"(a), "l"(b), "l"(c));
    return d;
}
__device__ __forceinline__ unsigned long long pack2(float lo, float hi) {
    unsigned long long p;
    asm("mov.b64 %0, {%1, %2};" : "=l"(p) : "r"(__float_as_uint(lo)), "r"(__float_as_uint(hi)));
    return p;
}
__device__ __forceinline__ void unpack2(unsigned long long p, float& lo, float& hi) {
    unsigned int l, h;
    asm("mov.b64 {%0, %1}, %2;" : "=r"(l), "=r"(h) : "l"(p));
    lo = __uint_as_float(l); hi = __uint_as_float(h);
}

// ---------------- CSR build ------------------------------------------------------
__global__ void __launch_bounds__(256) csr_zero() {
    int i = blockIdx.x * 256 + threadIdx.x;
    if (i < N_NODES) { g_cnt[i] = 0; g_cur[i] = 0; }
}

__global__ void __launch_bounds__(256) csr_hist(const int* __restrict__ ei) {
    int e = blockIdx.x * 256 + threadIdx.x;
    if (e < N_EDGES) atomicAdd(&g_cnt[ei[N_EDGES + e]], 1);
}

__global__ void __launch_bounds__(1024) csr_scan() {
    __shared__ int part[1024];
    const int t = threadIdx.x;
    const int CH = 30;
    int base = t * CH;
    int local[CH];
    int sum = 0;
    #pragma unroll
    for (int i = 0; i < CH; i++) {
        int idx = base + i;
        int v = (idx < N_NODES) ? g_cnt[idx] : 0;
        local[i] = sum;
        sum += v;
    }
    part[t] = sum;
    __syncthreads();
    for (int off = 1; off < 1024; off <<= 1) {
        int v = (t >= off) ? part[t - off] : 0;
        __syncthreads();
        part[t] += v;
        __syncthreads();
    }
    int exoff = part[t] - sum;
    #pragma unroll
    for (int i = 0; i < CH; i++) {
        int idx = base + i;
        if (idx < N_NODES) g_row[idx] = exoff + local[i];
    }
    if (t == 1023) g_row[N_NODES] = part[1023];
}

__global__ void __launch_bounds__(256) csr_scatter(
    const int* __restrict__ ei, const float* __restrict__ ea)
{
    int e = blockIdx.x * 256 + threadIdx.x;
    if (e >= N_EDGES) return;
    int s = ei[e];
    int d = ei[N_EDGES + e];
    int pos = g_row[d] + atomicAdd(&g_cur[d], 1);
    g_edge[pos] = make_int2(s, __float_as_int(ea[e]));
}

// ---------------- packed GEMM tail + hb2 epilogue --------------------------------
// out[n][t] = acc + bias[t]; also writes g_hb2[n][t] = (out + be[t]) * log2e.
__device__ __forceinline__ void gemm128_tail_T(
    float (*sInT)[SIN_STRIDE], float (*sW)[128],
    const float* __restrict__ W, const float* __restrict__ bias,
    const float* __restrict__ be,
    float* __restrict__ out, int nb, int t)
{
    unsigned long long accp[16];
    #pragma unroll
    for (int j = 0; j < 16; j++) accp[j] = 0ull;

    for (int k0 = 0; k0 < 128; k0 += 64) {
        __syncthreads();
        const float4* Wsrc = (const float4*)(W + k0 * 128);
        float4*       Wdst = (float4*)&sW[0][0];
        #pragma unroll
        for (int i = 0; i < 16; i++) Wdst[t + i * 128] = Wsrc[t + i * 128];
        __syncthreads();

        #pragma unroll 4
        for (int k = 0; k < 64; k++) {
            float w = sW[k][t];
            unsigned long long wp = pack2(w, w);
            const unsigned long long* arow =
                (const unsigned long long*)&sInT[k0 + k][0];
            #pragma unroll
            for (int j = 0; j < 16; j++)
                accp[j] = ffma2(arow[j], wp, accp[j]);
        }
    }
    float b  = bias[t];
    float bev = be[t];
    #pragma unroll
    for (int j = 0; j < 16; j++) {
        float lo, hi;
        unpack2(accp[j], lo, hi);
        int n0 = nb + 2 * j;
        int n1 = n0 + 1;
        if (n0 < N_NODES) {
            float v = lo + b;
            out[n0 * D + t]   = v;
            g_hb2[n0 * D + t] = (v + bev) * LOG2E;
        }
        if (n1 < N_NODES) {
            float v = hi + b;
            out[n1 * D + t]   = v;
            g_hb2[n1 * D + t] = (v + bev) * LOG2E;
        }
    }
}

// ---------------- node encoder: h0 = relu(x@Wn1+bn1)@Wn2+bn2 -> g_hA ------------
__global__ void __launch_bounds__(128) node_encoder(
    const float* __restrict__ x,
    const float* __restrict__ Wn1, const float* __restrict__ bn1,
    const float* __restrict__ Wn2, const float* __restrict__ bn2,
    const float* __restrict__ be)
{
    __shared__ float sInT[128][SIN_STRIDE];
    __shared__ float sW  [64][128];
    int nb = blockIdx.x * 32;
    int t  = threadIdx.x;

    float w[7];
    #pragma unroll
    for (int j = 0; j < 7; j++) w[j] = Wn1[j * D + t];
    float b1 = bn1[t];

    for (int n = 0; n < 32; n++) {
        int node = nb + n;
        float v = 0.f;
        if (node < N_NODES) {
            float s = b1;
            #pragma unroll
            for (int j = 0; j < 7; j++) s = fmaf(x[node * 7 + j], w[j], s);
            v = fmaxf(s, 0.f);
        }
        sInT[t][n] = v;
    }
    gemm128_tail_T(sInT, sW, Wn2, bn2, be, g_hA, nb, t);
}

// ---------------- gather + segment softmax, base-2 fast path ---------------------
// hb2 rows hold (h+be)*log2e. Fast path: e = exp2(msg2) directly, no max (e>=1,
// overflow only if msg>88.7). Warp ballot on isinf(d) triggers the cold online-
// max fallback for that node. agg = (n/d)*ln2.
__global__ void __launch_bounds__(256) genconv_gather(
    int hsel, const float* __restrict__ We)
{
    const float* __restrict__ h = hsel ? g_hB : g_hA;
    int node = blockIdx.x * 8 + (threadIdx.x >> 5);
    if (node >= N_NODES) return;
    int lane = threadIdx.x & 31;
    int q    = lane << 2;

    int beg = g_row[node];
    int end = g_row[node + 1];

    float4 wt = *(const float4*)(We + q);
    float4 wv = make_float4(wt.x * LOG2E, wt.y * LOG2E, wt.z * LOG2E, wt.w * LOG2E);

    float d0 = 0.f, d1 = 0.f, d2 = 0.f, d3 = 0.f;
    float n0 = 0.f, n1 = 0.f, n2 = 0.f, n3 = 0.f;

    for (int k = beg; k < end; k++) {
        int2   e  = g_edge[k];
        float  a  = __int_as_float(e.y);
        float4 hv = *(const float4*)(g_hb2 + e.x * D + q);

        float s0 = fmaxf(fmaf(a, wv.x, hv.x), 0.f) + E2;
        float s1 = fmaxf(fmaf(a, wv.y, hv.y), 0.f) + E2;
        float s2 = fmaxf(fmaf(a, wv.z, hv.z), 0.f) + E2;
        float s3 = fmaxf(fmaf(a, wv.w, hv.w), 0.f) + E2;
        float e0 = exp2f(s0);
        float e1 = exp2f(s1);
        float e2 = exp2f(s2);
        float e3 = exp2f(s3);
        d0 += e0; n0 = fmaf(e0, s0, n0);
        d1 += e1; n1 = fmaf(e1, s1, n1);
        d2 += e2; n2 = fmaf(e2, s2, n2);
        d3 += e3; n3 = fmaf(e3, s3, n3);
    }

    // overflow safety net (cold): redo with online max if any lane's d hit inf
    unsigned bad = __ballot_sync(0xffffffffu,
        isinf(d0) | isinf(d1) | isinf(d2) | isinf(d3));
    if (bad) {
        float m[4] = {-1e30f, -1e30f, -1e30f, -1e30f};
        float dd[4] = {0.f, 0.f, 0.f, 0.f};
        float nn[4] = {0.f, 0.f, 0.f, 0.f};
        for (int k = beg; k < end; k++) {
            int2   e  = g_edge[k];
            float  a  = __int_as_float(e.y);
            float4 hv = *(const float4*)(g_hb2 + e.x * D + q);
            float s[4];
            s[0] = fmaxf(fmaf(a, wv.x, hv.x), 0.f) + E2;
            s[1] = fmaxf(fmaf(a, wv.y, hv.y), 0.f) + E2;
            s[2] = fmaxf(fmaf(a, wv.z, hv.z), 0.f) + E2;
            s[3] = fmaxf(fmaf(a, wv.w, hv.w), 0.f) + E2;
            #pragma unroll
            for (int c = 0; c < 4; c++) {
                float mn = fmaxf(m[c], s[c]);
                float eo = exp2f(m[c] - mn);
                float en = exp2f(s[c] - mn);
                dd[c] = fmaf(dd[c], eo, en);
                nn[c] = fmaf(nn[c], eo, en * s[c]);
                m[c] = mn;
            }
        }
        d0 = dd[0]; d1 = dd[1]; d2 = dd[2]; d3 = dd[3];
        n0 = nn[0]; n1 = nn[1]; n2 = nn[2]; n3 = nn[3];
    }

    float4 hn = *(const float4*)(h + node * D + q);
    float4 o;
    o.x = (d0 > 0.f ? (n0 / d0) * LN2 : 0.f) + hn.x;
    o.y = (d1 > 0.f ? (n1 / d1) * LN2 : 0.f) + hn.y;
    o.z = (d2 > 0.f ? (n2 / d2) * LN2 : 0.f) + hn.z;
    o.w = (d3 > 0.f ? (n3 / d3) * LN2 : 0.f) + hn.w;
    *(float4*)(g_pre + node * D + q) = o;
}

// ---------------- node update: h_out = g_pre @ Wg + bg --------------------------
__global__ void __launch_bounds__(128) node_update(
    int hsel, const float* __restrict__ Wg_l, const float* __restrict__ bg_l,
    const float* __restrict__ be)
{
    float* h_out = hsel ? g_hA : g_hB;

    __shared__ float sInT[128][SIN_STRIDE];
    __shared__ float sW  [64][128];
    int nb = blockIdx.x * 32;
    int t  = threadIdx.x;

    for (int n = 0; n < 32; n++) {
        int node = nb + n;
        sInT[t][n] = (node < N_NODES) ? g_pre[node * D + t] : 0.f;
    }
    gemm128_tail_T(sInT, sW, Wg_l, bg_l, be, h_out, nb, t);
}

// ---------------- output head: out = h @ Wo + bo  (warp per node) ---------------
__global__ void __launch_bounds__(256) head_kernel(
    const float* __restrict__ Wo, const float* __restrict__ bo,
    float* __restrict__ out)
{
    int warp = (blockIdx.x * 256 + threadIdx.x) >> 5;
    int lane = threadIdx.x & 31;
    if (warp >= N_NODES) return;
    const float* row = g_hA + warp * D;   // after 4 layers h lives in g_hA

    float a0 = 0.f, a1 = 0.f, a2 = 0.f;
    #pragma unroll
    for (int k = lane; k < D; k += 32) {
        float v = row[k];
        a0 = fmaf(v, Wo[k * 3 + 0], a0);
        a1 = fmaf(v, Wo[k * 3 + 1], a1);
        a2 = fmaf(v, Wo[k * 3 + 2], a2);
    }
    #pragma unroll
    for (int off = 16; off; off >>= 1) {
        a0 += __shfl_down_sync(0xffffffffu, a0, off);
        a1 += __shfl_down_sync(0xffffffffu, a1, off);
        a2 += __shfl_down_sync(0xffffffffu, a2, off);
    }
    if (lane == 0) {
        out[warp * 3 + 0] = a0 + bo[0];
        out[warp * 3 + 1] = a1 + bo[1];
        out[warp * 3 + 2] = a2 + bo[2];
    }
}

// ---------------- launch --------------------------------------------------------
extern "C" void kernel_launch(void* const* d_in, const int* in_sizes, int n_in,
                              void* d_out, int out_size)
{
    const float* x   = (const float*)d_in[0];
    const int*   ei  = (const int*)  d_in[1];
    const float* ea  = (const float*)d_in[2];
    const float* Wn1 = (const float*)d_in[3];
    const float* bn1 = (const float*)d_in[4];
    const float* Wn2 = (const float*)d_in[5];
    const float* bn2 = (const float*)d_in[6];
    const float* We  = (const float*)d_in[7];
    const float* be  = (const float*)d_in[8];
    const float* Wg  = (const float*)d_in[9];
    const float* bg  = (const float*)d_in[10];
    const float* Wo  = (const float*)d_in[11];
    const float* bo  = (const float*)d_in[12];
    float* out = (float*)d_out;

    const int NODE_BLOCKS   = (N_NODES + 31) / 32;        // 938
    const int EDGE_BLOCKS   = (N_EDGES + 255) / 256;      // 1875
    const int CNT_BLOCKS    = (N_NODES + 255) / 256;      // 118
    const int GATHER_BLOCKS = (N_NODES + 7) / 8;          // 3750 (8 warps/block)

    // CSR build (graph constant; recomputed every call for determinism)
    csr_zero   <<<CNT_BLOCKS, 256>>>();
    csr_hist   <<<EDGE_BLOCKS, 256>>>(ei);
    csr_scan   <<<1, 1024>>>();
    csr_scatter<<<EDGE_BLOCKS, 256>>>(ei, ea);

    node_encoder<<<NODE_BLOCKS, 128>>>(x, Wn1, bn1, Wn2, bn2, be);

    for (int l = 0; l < 4; l++) {
        int hsel = l & 1;   // 0: h in g_hA, 1: h in g_hB
        genconv_gather<<<GATHER_BLOCKS, 256>>>(hsel, We);
        node_update   <<<NODE_BLOCKS, 128>>>(hsel, Wg + (size_t)l * D * D, bg + (size_t)l * D, be);
    }

    head_kernel<<<(N_NODES * 32 + 255) / 256, 256>>>(Wo, bo, out);
}